// round 10
// baseline (speedup 1.0000x reference)
#include <cuda_runtime.h>
#include <cstdint>

// ---------------------------------------------------------------------------
// TernaryLinear, single fused kernel (plain sm_100 toolchain: no tcgen05).
// Each GEMM CTA first PRODUCES a slice of the quantized operands, then spins
// on per-band counters, then runs the R6 IMMA GEMM mainloop (measured best:
// tensor=82.5%, 311us).
//   x band bm  : produced by CTAs (bm, 0..31), 4 rows each (warp-per-row)
//   wq band bn : produced by CTAs (0..7, bn), 16 rows each
// Flags zeroed per launch by a cudaMemsetAsync graph node.
// ---------------------------------------------------------------------------

#define T_TOKENS 8192
#define KDIM     4096
#define ODIM     4096

#define BM 128
#define BN 128
#define BK 64              // int8 elems per k-tile
#define NSTAGE 4
#define KT (KDIM / BK)     // 64
#define A_BYTES (BM * BK)  // 8 KB
#define B_BYTES (BN * BK)  // 8 KB
#define STAGE_BYTES (A_BYTES + B_BYTES)    // 16 KB
#define DYN_SMEM (NSTAGE * STAGE_BYTES + 128)

__device__ __align__(128) int8_t g_xq[(size_t)T_TOKENS * KDIM];
__device__ __align__(128) int8_t g_wq[(size_t)ODIM * KDIM];
__device__ float g_ascale[T_TOKENS];
__device__ int   g_cnt[96];          // [0..63]: xcnt per bm ; [64..95]: wcnt per bn

// --------------------------- helpers ---------------------------------------
__device__ __forceinline__ uint32_t cvta_s(const void* p) {
    return (uint32_t)__cvta_generic_to_shared(p);
}
__device__ __forceinline__ void cp_async16(uint32_t d, const void* s) {
    asm volatile("cp.async.cg.shared.global [%0], [%1], 16;\n" :: "r"(d), "l"(s));
}
__device__ __forceinline__ void cp_commit() {
    asm volatile("cp.async.commit_group;\n" ::: "memory");
}
template <int N> __device__ __forceinline__ void cp_wait() {
    asm volatile("cp.async.wait_group %0;\n" :: "n"(N) : "memory");
}
__device__ __forceinline__ void ldsm_x4(uint32_t* r, uint32_t addr) {
    asm volatile("ldmatrix.sync.aligned.m8n8.x4.shared.b16 {%0,%1,%2,%3}, [%4];"
                 : "=r"(r[0]), "=r"(r[1]), "=r"(r[2]), "=r"(r[3]) : "r"(addr));
}
__device__ __forceinline__ void mma16832(int* d, const uint32_t* a,
                                         uint32_t b0, uint32_t b1) {
    asm volatile(
        "mma.sync.aligned.m16n8k32.row.col.s32.s8.s8.s32 "
        "{%0,%1,%2,%3}, {%4,%5,%6,%7}, {%8,%9}, {%0,%1,%2,%3};\n"
        : "+r"(d[0]), "+r"(d[1]), "+r"(d[2]), "+r"(d[3])
        : "r"(a[0]), "r"(a[1]), "r"(a[2]), "r"(a[3]), "r"(b0), "r"(b1));
}
__device__ __forceinline__ signed char q8(float v, float inv) {
    return (signed char)(int)fminf(fmaxf(rintf(v * inv), -127.0f), 127.0f);
}

// ---------------------------------------------------------------------------
__global__ __launch_bounds__(128, 2)
void gemm_fused_kernel(const float* __restrict__ x,
                       const float* __restrict__ w,
                       const float* __restrict__ wscale_p,
                       const float* __restrict__ bias,
                       float* __restrict__ out) {
    extern __shared__ int8_t smem_raw[];
    const uint32_t smem_u = (cvta_s(smem_raw) + 127u) & ~127u;

    const int tid  = threadIdx.x;
    const int lane = tid & 31;
    const int wid  = tid >> 5;
    const int wm   = wid & 1;
    const int wn   = wid >> 1;
    const int bm   = blockIdx.y;     // 0..63
    const int bn   = blockIdx.x;     // 0..31

    // ===================== PRODUCE: x slice (warp-per-row) ==================
    {
        const int row = bm * BM + bn * 4 + wid;          // 4 rows per CTA
        const float4* xr = reinterpret_cast<const float4*>(x + (size_t)row * KDIM);
        float m = 0.0f;
        #pragma unroll 4
        for (int i = 0; i < 32; i++) {
            float4 v = xr[lane + (i << 5)];
            m = fmaxf(m, fmaxf(fmaxf(fabsf(v.x), fabsf(v.y)),
                               fmaxf(fabsf(v.z), fabsf(v.w))));
        }
        #pragma unroll
        for (int o = 16; o; o >>= 1) m = fmaxf(m, __shfl_xor_sync(0xffffffffu, m, o));
        const float sc  = fmaxf(m, 1e-10f) / 127.0f;
        const float inv = 1.0f / sc;
        if (lane == 0) g_ascale[row] = sc;
        char4* oq = reinterpret_cast<char4*>(g_xq + (size_t)row * KDIM);
        #pragma unroll 4
        for (int i = 0; i < 32; i++) {
            float4 v = xr[lane + (i << 5)];              // L1 hit (16KB row)
            oq[lane + (i << 5)] = make_char4(q8(v.x, inv), q8(v.y, inv),
                                             q8(v.z, inv), q8(v.w, inv));
        }
    }
    // ===================== PRODUCE: w slice (bm < 8 only) ===================
    if (bm < 8) {
        #pragma unroll 1
        for (int r = 0; r < 4; r++) {
            const int row = bn * BN + bm * 16 + wid * 4 + r;
            const float4* wr = reinterpret_cast<const float4*>(w + (size_t)row * KDIM);
            char4* oq = reinterpret_cast<char4*>(g_wq + (size_t)row * KDIM);
            #pragma unroll 4
            for (int i = 0; i < 32; i++) {
                float4 v = wr[lane + (i << 5)];
                oq[lane + (i << 5)] = make_char4(
                    (signed char)(int)v.x, (signed char)(int)v.y,
                    (signed char)(int)v.z, (signed char)(int)v.w);
            }
        }
    }
    __threadfence();            // release this thread's stores (gpu scope)
    __syncthreads();            // all CTA stores released
    if (tid == 0) {
        atomicAdd(&g_cnt[bm], 1);
        if (bm < 8) atomicAdd(&g_cnt[64 + bn], 1);
        while (atomicAdd(&g_cnt[bm], 0) < 32)     __nanosleep(128);
        while (atomicAdd(&g_cnt[64 + bn], 0) < 8) __nanosleep(128);
        __threadfence();        // acquire
    }
    __syncthreads();

    // ===================== CONSUME: R6 IMMA GEMM ============================
    const int8_t* Ag = g_xq + (size_t)bm * BM * KDIM;
    const int8_t* Bg = g_wq + (size_t)bn * BN * KDIM;

    auto load_tile = [&](int st, int kt) {
        const uint32_t sb = smem_u + st * STAGE_BYTES;
        const int koff = kt * BK;
        #pragma unroll
        for (int r = 0; r < 4; r++) {
            const int id  = tid + (r << 7);
            const int row = id >> 2;
            const int c   = id & 3;
            const uint32_t phys = (uint32_t)((c ^ ((row >> 1) & 3)) << 4);
            cp_async16(sb + row * BK + phys,
                       Ag + (size_t)row * KDIM + koff + (c << 4));
            cp_async16(sb + A_BYTES + row * BK + phys,
                       Bg + (size_t)row * KDIM + koff + (c << 4));
        }
    };

    uint32_t a_off[4];
    {
        const int m  = lane >> 3;
        const int rr = ((m & 1) << 3) + (lane & 7);
        const int cb = m >> 1;
        #pragma unroll
        for (int mi = 0; mi < 4; mi++) {
            const int row = wm * 64 + mi * 16 + rr;
            a_off[mi] = (uint32_t)(row * BK + ((cb ^ ((row >> 1) & 3)) << 4));
        }
    }
    uint32_t b_off[4];
    {
        const int m  = lane >> 3;
        const int cr = ((m >> 1) << 3) + (lane & 7);
        const int cb = m & 1;
        #pragma unroll
        for (int n2 = 0; n2 < 4; n2++) {
            const int col = wn * 64 + n2 * 16 + cr;
            b_off[n2] = (uint32_t)(A_BYTES + col * BK + ((cb ^ ((col >> 1) & 3)) << 4));
        }
    }

    int acc[4][8][4] = {};

    load_tile(0, 0); cp_commit();
    load_tile(1, 1); cp_commit();
    load_tile(2, 2); cp_commit();

    for (int kt = 0; kt < KT; kt++) {
        cp_wait<2>();
        __syncthreads();

        const uint32_t sb = smem_u + (uint32_t)((kt & (NSTAGE - 1)) * STAGE_BYTES);

        uint32_t a[4][4], b[4][4];
        #pragma unroll
        for (int mi = 0; mi < 4; mi++) ldsm_x4(a[mi], sb + a_off[mi]);
        #pragma unroll
        for (int n2 = 0; n2 < 4; n2++)  ldsm_x4(b[n2], sb + b_off[n2]);

        const int nxt = kt + 3;
        if (nxt < KT) load_tile(nxt & (NSTAGE - 1), nxt);
        cp_commit();

        #pragma unroll
        for (int mi = 0; mi < 4; mi++) {
            #pragma unroll
            for (int ni = 0; ni < 8; ni++) {
                const uint32_t* bb = b[ni >> 1];
                const int o = (ni & 1) << 1;
                mma16832(acc[mi][ni], a[mi], bb[o], bb[o + 1]);
            }
        }

        #pragma unroll
        for (int mi = 0; mi < 4; mi++) ldsm_x4(a[mi], sb + (a_off[mi] ^ 32u));
        #pragma unroll
        for (int n2 = 0; n2 < 4; n2++)  ldsm_x4(b[n2], sb + (b_off[n2] ^ 32u));
        #pragma unroll
        for (int mi = 0; mi < 4; mi++) {
            #pragma unroll
            for (int ni = 0; ni < 8; ni++) {
                const uint32_t* bb = b[ni >> 1];
                const int o = (ni & 1) << 1;
                mma16832(acc[mi][ni], a[mi], bb[o], bb[o + 1]);
            }
        }
    }

    // epilogue: y = acc * act_scale[row] * w_scale + bias[col]
    const float ws = __ldg(wscale_p);
    #pragma unroll
    for (int mi = 0; mi < 4; mi++) {
        const int r0 = bm * BM + wm * 64 + mi * 16 + (lane >> 2);
        const float s0 = g_ascale[r0] * ws;
        const float s1 = g_ascale[r0 + 8] * ws;
        #pragma unroll
        for (int ni = 0; ni < 8; ni++) {
            const int c = bn * BN + wn * 64 + ni * 8 + ((lane & 3) << 1);
            const float b0 = __ldg(bias + c);
            const float b1 = __ldg(bias + c + 1);
            float2 v0 = make_float2((float)acc[mi][ni][0] * s0 + b0,
                                    (float)acc[mi][ni][1] * s0 + b1);
            float2 v1 = make_float2((float)acc[mi][ni][2] * s1 + b0,
                                    (float)acc[mi][ni][3] * s1 + b1);
            *reinterpret_cast<float2*>(out + (size_t)r0 * ODIM + c)       = v0;
            *reinterpret_cast<float2*>(out + (size_t)(r0 + 8) * ODIM + c) = v1;
        }
    }
}

// ---------------------------------------------------------------------------
extern "C" void kernel_launch(void* const* d_in, const int* in_sizes, int n_in,
                              void* d_out, int out_size) {
    const float* x      = (const float*)d_in[0];   // [8192, 4096]
    const float* w_t    = (const float*)d_in[1];   // [4096, 4096]
    const float* wscale = (const float*)d_in[2];   // scalar
    const float* bias   = (const float*)d_in[3];   // [4096]
    float* out          = (float*)d_out;           // [8192, 4096]

    // zero the producer-consumer counters every launch (graph-legal memset node)
    void* cnt_addr = nullptr;
    cudaGetSymbolAddress(&cnt_addr, g_cnt);
    cudaMemsetAsync(cnt_addr, 0, sizeof(int) * 96);

    cudaFuncSetAttribute(gemm_fused_kernel,
                         cudaFuncAttributeMaxDynamicSharedMemorySize, DYN_SMEM);
    dim3 grid(ODIM / BN, T_TOKENS / BM);   // (32, 64) -> linear id = bn + 32*bm
    gemm_fused_kernel<<<grid, 128, DYN_SMEM>>>(x, w_t, wscale, bias, out);
}

// round 11
// speedup vs baseline: 1.3463x; 1.3463x over previous
#include <cuda_runtime.h>
#include <cstdint>

// ---------------------------------------------------------------------------
// TernaryLinear, legacy-IMMA path (plain sm_100 toolchain: no tcgen05).
//   K1 (fused): per-row absmax int8 quant of x  AND  f32->int8 weight convert
//   K2: int8 GEMM mma.sync.m16n8k32, 4 warps @ 64x64, BK=64,
//       6-stage cp.async pipeline (lead 5), 2 CTA/SM.  (R6 + deeper staging)
// ---------------------------------------------------------------------------

#define T_TOKENS 8192
#define KDIM     4096
#define ODIM     4096

#define BM 128
#define BN 128
#define BK 64              // int8 elems per k-tile
#define NSTAGE 6
#define LEAD 5
#define KT (KDIM / BK)     // 64
#define A_BYTES (BM * BK)  // 8 KB
#define B_BYTES (BN * BK)  // 8 KB
#define STAGE_BYTES (A_BYTES + B_BYTES)    // 16 KB
#define DYN_SMEM (NSTAGE * STAGE_BYTES + 128)   // 96 KB + pad

#define W_BLOCKS ((ODIM * KDIM / 4) / 256)

__device__ __align__(128) int8_t g_xq[(size_t)T_TOKENS * KDIM];
__device__ __align__(128) int8_t g_wq[(size_t)ODIM * KDIM];
__device__ float g_ascale[T_TOKENS];

// --------------------------- helpers ---------------------------------------
__device__ __forceinline__ uint32_t cvta_s(const void* p) {
    return (uint32_t)__cvta_generic_to_shared(p);
}
__device__ __forceinline__ void cp_async16(uint32_t d, const void* s) {
    asm volatile("cp.async.cg.shared.global [%0], [%1], 16;\n" :: "r"(d), "l"(s));
}
__device__ __forceinline__ void cp_commit() {
    asm volatile("cp.async.commit_group;\n" ::: "memory");
}
template <int N> __device__ __forceinline__ void cp_wait() {
    asm volatile("cp.async.wait_group %0;\n" :: "n"(N) : "memory");
}
__device__ __forceinline__ void ldsm_x4(uint32_t* r, uint32_t addr) {
    asm volatile("ldmatrix.sync.aligned.m8n8.x4.shared.b16 {%0,%1,%2,%3}, [%4];"
                 : "=r"(r[0]), "=r"(r[1]), "=r"(r[2]), "=r"(r[3]) : "r"(addr));
}
__device__ __forceinline__ void mma16832(int* d, const uint32_t* a,
                                         uint32_t b0, uint32_t b1) {
    asm volatile(
        "mma.sync.aligned.m16n8k32.row.col.s32.s8.s8.s32 "
        "{%0,%1,%2,%3}, {%4,%5,%6,%7}, {%8,%9}, {%0,%1,%2,%3};\n"
        : "+r"(d[0]), "+r"(d[1]), "+r"(d[2]), "+r"(d[3])
        : "r"(a[0]), "r"(a[1]), "r"(a[2]), "r"(a[3]), "r"(b0), "r"(b1));
}
__device__ __forceinline__ signed char q8(float v, float inv) {
    return (signed char)(int)fminf(fmaxf(rintf(v * inv), -127.0f), 127.0f);
}

// ---------------------------------------------------------------------------
// K1 fused: blocks [0, 8192) quantize x rows; rest convert w.
// ---------------------------------------------------------------------------
__global__ __launch_bounds__(256) void quant_fused_kernel(
    const float* __restrict__ x, const float* __restrict__ w) {
    if (blockIdx.x < T_TOKENS) {
        const int row = blockIdx.x;
        const float4* xr = reinterpret_cast<const float4*>(x + (size_t)row * KDIM);
        const int base = threadIdx.x << 2;

        float4 v[4];
        float m = 0.0f;
        #pragma unroll
        for (int j = 0; j < 4; j++) {
            v[j] = xr[base + j];
            m = fmaxf(m, fmaxf(fmaxf(fabsf(v[j].x), fabsf(v[j].y)),
                               fmaxf(fabsf(v[j].z), fabsf(v[j].w))));
        }
        #pragma unroll
        for (int o = 16; o; o >>= 1) m = fmaxf(m, __shfl_xor_sync(0xffffffffu, m, o));

        __shared__ float warpmax[8];
        __shared__ float s_inv;
        const int wid = threadIdx.x >> 5, lane = threadIdx.x & 31;
        if (lane == 0) warpmax[wid] = m;
        __syncthreads();
        if (threadIdx.x == 0) {
            float mm = warpmax[0];
            #pragma unroll
            for (int i = 1; i < 8; i++) mm = fmaxf(mm, warpmax[i]);
            float sc = fmaxf(mm, 1e-10f) / 127.0f;
            g_ascale[row] = sc;
            s_inv = 1.0f / sc;
        }
        __syncthreads();
        const float inv = s_inv;

        uint32_t p[4];
        #pragma unroll
        for (int j = 0; j < 4; j++) {
            char4 c = make_char4(q8(v[j].x, inv), q8(v[j].y, inv),
                                 q8(v[j].z, inv), q8(v[j].w, inv));
            p[j] = *reinterpret_cast<uint32_t*>(&c);
        }
        reinterpret_cast<uint4*>(g_xq + (size_t)row * KDIM)[threadIdx.x] =
            make_uint4(p[0], p[1], p[2], p[3]);
    } else {
        const size_t i = (size_t)(blockIdx.x - T_TOKENS) * 256 + threadIdx.x;
        const float4 v = reinterpret_cast<const float4*>(w)[i];
        char4 c;
        c.x = (signed char)(int)v.x;
        c.y = (signed char)(int)v.y;
        c.z = (signed char)(int)v.z;
        c.w = (signed char)(int)v.w;
        reinterpret_cast<char4*>(g_wq)[i] = c;
    }
}

// ---------------------------------------------------------------------------
// K2: int8 GEMM. C[T,O] = xq[T,K] @ wq[O,K]^T
// smem rows 64B = 4 chunks of 16B; swizzle: phys_chunk = c ^ ((row>>1)&3)
// ---------------------------------------------------------------------------
__global__ __launch_bounds__(128, 2)
void gemm_kernel(const float* __restrict__ wscale_p,
                 const float* __restrict__ bias,
                 float* __restrict__ out) {
    extern __shared__ int8_t smem_raw[];
    const uint32_t smem_u = (cvta_s(smem_raw) + 127u) & ~127u;

    const int tid  = threadIdx.x;
    const int lane = tid & 31;
    const int wid  = tid >> 5;
    const int wm   = wid & 1;
    const int wn   = wid >> 1;
    const int bm   = blockIdx.y;
    const int bn   = blockIdx.x;

    const int8_t* Ag = g_xq + (size_t)bm * BM * KDIM;
    const int8_t* Bg = g_wq + (size_t)bn * BN * KDIM;

    auto load_tile = [&](int st, int kt) {
        const uint32_t sb = smem_u + st * STAGE_BYTES;
        const int koff = kt * BK;
        #pragma unroll
        for (int r = 0; r < 4; r++) {
            const int id  = tid + (r << 7);
            const int row = id >> 2;
            const int c   = id & 3;
            const uint32_t phys = (uint32_t)((c ^ ((row >> 1) & 3)) << 4);
            cp_async16(sb + row * BK + phys,
                       Ag + (size_t)row * KDIM + koff + (c << 4));
            cp_async16(sb + A_BYTES + row * BK + phys,
                       Bg + (size_t)row * KDIM + koff + (c << 4));
        }
    };

    // LDSM offsets (ks=0; ks=1 via ^32)
    uint32_t a_off[4];
    {
        const int m  = lane >> 3;
        const int rr = ((m & 1) << 3) + (lane & 7);
        const int cb = m >> 1;
        #pragma unroll
        for (int mi = 0; mi < 4; mi++) {
            const int row = wm * 64 + mi * 16 + rr;
            a_off[mi] = (uint32_t)(row * BK + ((cb ^ ((row >> 1) & 3)) << 4));
        }
    }
    uint32_t b_off[4];
    {
        const int m  = lane >> 3;
        const int cr = ((m >> 1) << 3) + (lane & 7);
        const int cb = m & 1;
        #pragma unroll
        for (int n2 = 0; n2 < 4; n2++) {
            const int col = wn * 64 + n2 * 16 + cr;
            b_off[n2] = (uint32_t)(A_BYTES + col * BK + ((cb ^ ((col >> 1) & 3)) << 4));
        }
    }

    int acc[4][8][4] = {};

    // prologue: prefetch LEAD=5 tiles into stages 0..4
    #pragma unroll
    for (int t = 0; t < LEAD; t++) { load_tile(t, t); cp_commit(); }

    // stage index of tile kt, maintained incrementally (kt % 6)
    int st_cur = 0;
    int st_pre = LEAD;     // stage for tile kt+LEAD  ((kt+5) % 6)

    for (int kt = 0; kt < KT; kt++) {
        // commits so far = LEAD + kt; wait<LEAD-1> => tiles 0..kt complete
        cp_wait<LEAD - 1>();
        __syncthreads();

        const uint32_t sb = smem_u + (uint32_t)(st_cur * STAGE_BYTES);

        // ks=0 fragment loads first (latency overlaps cp.async burst below)
        uint32_t a[4][4], b[4][4];
        #pragma unroll
        for (int mi = 0; mi < 4; mi++) ldsm_x4(a[mi], sb + a_off[mi]);
        #pragma unroll
        for (int n2 = 0; n2 < 4; n2++)  ldsm_x4(b[n2], sb + b_off[n2]);

        const int nxt = kt + LEAD;
        if (nxt < KT) load_tile(st_pre, nxt);
        cp_commit();

        #pragma unroll
        for (int mi = 0; mi < 4; mi++) {
            #pragma unroll
            for (int ni = 0; ni < 8; ni++) {
                const uint32_t* bb = b[ni >> 1];
                const int o = (ni & 1) << 1;
                mma16832(acc[mi][ni], a[mi], bb[o], bb[o + 1]);
            }
        }

        // ks = 1
        #pragma unroll
        for (int mi = 0; mi < 4; mi++) ldsm_x4(a[mi], sb + (a_off[mi] ^ 32u));
        #pragma unroll
        for (int n2 = 0; n2 < 4; n2++)  ldsm_x4(b[n2], sb + (b_off[n2] ^ 32u));
        #pragma unroll
        for (int mi = 0; mi < 4; mi++) {
            #pragma unroll
            for (int ni = 0; ni < 8; ni++) {
                const uint32_t* bb = b[ni >> 1];
                const int o = (ni & 1) << 1;
                mma16832(acc[mi][ni], a[mi], bb[o], bb[o + 1]);
            }
        }

        st_cur = (st_cur == NSTAGE - 1) ? 0 : st_cur + 1;
        st_pre = (st_pre == NSTAGE - 1) ? 0 : st_pre + 1;
    }

    // epilogue: y = acc * act_scale[row] * w_scale + bias[col]
    const float ws = __ldg(wscale_p);
    #pragma unroll
    for (int mi = 0; mi < 4; mi++) {
        const int r0 = bm * BM + wm * 64 + mi * 16 + (lane >> 2);
        const float s0 = g_ascale[r0] * ws;
        const float s1 = g_ascale[r0 + 8] * ws;
        #pragma unroll
        for (int ni = 0; ni < 8; ni++) {
            const int c = bn * BN + wn * 64 + ni * 8 + ((lane & 3) << 1);
            const float b0 = __ldg(bias + c);
            const float b1 = __ldg(bias + c + 1);
            float2 v0 = make_float2((float)acc[mi][ni][0] * s0 + b0,
                                    (float)acc[mi][ni][1] * s0 + b1);
            float2 v1 = make_float2((float)acc[mi][ni][2] * s1 + b0,
                                    (float)acc[mi][ni][3] * s1 + b1);
            *reinterpret_cast<float2*>(out + (size_t)r0 * ODIM + c)       = v0;
            *reinterpret_cast<float2*>(out + (size_t)(r0 + 8) * ODIM + c) = v1;
        }
    }
}

// ---------------------------------------------------------------------------
extern "C" void kernel_launch(void* const* d_in, const int* in_sizes, int n_in,
                              void* d_out, int out_size) {
    const float* x      = (const float*)d_in[0];   // [8192, 4096]
    const float* w_t    = (const float*)d_in[1];   // [4096, 4096]
    const float* wscale = (const float*)d_in[2];   // scalar
    const float* bias   = (const float*)d_in[3];   // [4096]
    float* out          = (float*)d_out;           // [8192, 4096]

    quant_fused_kernel<<<T_TOKENS + W_BLOCKS, 256>>>(x, w_t);

    cudaFuncSetAttribute(gemm_kernel, cudaFuncAttributeMaxDynamicSharedMemorySize,
                         DYN_SMEM);
    dim3 grid(ODIM / BN, T_TOKENS / BM);   // (32, 64)
    gemm_kernel<<<grid, 128, DYN_SMEM>>>(wscale, bias, out);
}

// round 12
// speedup vs baseline: 1.3792x; 1.0244x over previous
#include <cuda_runtime.h>
#include <cstdint>

// ---------------------------------------------------------------------------
// TernaryLinear, legacy-IMMA path (plain sm_100 toolchain: no tcgen05).
//   K1 (fused): per-row absmax int8 quant of x  AND  f32->int8 weight convert
//               (evict-first loads: single-use f32 streams kept out of L2)
//   K2: int8 GEMM mma.sync.m16n8k32, 4 warps @ 64x64, BK=64, 4-stage
//       cp.async, 2 CTA/SM  -- byte-identical to the measured-best R6 GEMM
//       (tensor pipe ~82.5% = ~85% of the SM-shared fallback-IMMA ceiling).
// ---------------------------------------------------------------------------

#define T_TOKENS 8192
#define KDIM     4096
#define ODIM     4096

#define BM 128
#define BN 128
#define BK 64              // int8 elems per k-tile
#define NSTAGE 4
#define KT (KDIM / BK)     // 64
#define A_BYTES (BM * BK)  // 8 KB
#define B_BYTES (BN * BK)  // 8 KB
#define STAGE_BYTES (A_BYTES + B_BYTES)    // 16 KB
#define DYN_SMEM (NSTAGE * STAGE_BYTES + 128)

#define W_BLOCKS ((ODIM * KDIM / 8) / 256)   // 8192 blocks, 2 float4/thread

__device__ __align__(128) int8_t g_xq[(size_t)T_TOKENS * KDIM];
__device__ __align__(128) int8_t g_wq[(size_t)ODIM * KDIM];
__device__ float g_ascale[T_TOKENS];

// --------------------------- helpers ---------------------------------------
__device__ __forceinline__ uint32_t cvta_s(const void* p) {
    return (uint32_t)__cvta_generic_to_shared(p);
}
__device__ __forceinline__ void cp_async16(uint32_t d, const void* s) {
    asm volatile("cp.async.cg.shared.global [%0], [%1], 16;\n" :: "r"(d), "l"(s));
}
__device__ __forceinline__ void cp_commit() {
    asm volatile("cp.async.commit_group;\n" ::: "memory");
}
template <int N> __device__ __forceinline__ void cp_wait() {
    asm volatile("cp.async.wait_group %0;\n" :: "n"(N) : "memory");
}
__device__ __forceinline__ void ldsm_x4(uint32_t* r, uint32_t addr) {
    asm volatile("ldmatrix.sync.aligned.m8n8.x4.shared.b16 {%0,%1,%2,%3}, [%4];"
                 : "=r"(r[0]), "=r"(r[1]), "=r"(r[2]), "=r"(r[3]) : "r"(addr));
}
__device__ __forceinline__ void mma16832(int* d, const uint32_t* a,
                                         uint32_t b0, uint32_t b1) {
    asm volatile(
        "mma.sync.aligned.m16n8k32.row.col.s32.s8.s8.s32 "
        "{%0,%1,%2,%3}, {%4,%5,%6,%7}, {%8,%9}, {%0,%1,%2,%3};\n"
        : "+r"(d[0]), "+r"(d[1]), "+r"(d[2]), "+r"(d[3])
        : "r"(a[0]), "r"(a[1]), "r"(a[2]), "r"(a[3]), "r"(b0), "r"(b1));
}
__device__ __forceinline__ signed char q8(float v, float inv) {
    return (signed char)(int)fminf(fmaxf(rintf(v * inv), -127.0f), 127.0f);
}
__device__ __forceinline__ float4 ldcs4(const float4* p) {
    return __ldcs(p);          // evict-first: single-use stream
}

// ---------------------------------------------------------------------------
// K1 fused: blocks [0, 8192) quantize x rows; blocks [8192, +8192) convert w
// (2 float4 per thread).
// ---------------------------------------------------------------------------
__global__ __launch_bounds__(256) void quant_fused_kernel(
    const float* __restrict__ x, const float* __restrict__ w) {
    if (blockIdx.x < T_TOKENS) {
        const int row = blockIdx.x;
        const float4* xr = reinterpret_cast<const float4*>(x + (size_t)row * KDIM);
        const int base = threadIdx.x << 2;

        float4 v[4];
        float m = 0.0f;
        #pragma unroll
        for (int j = 0; j < 4; j++) {
            v[j] = ldcs4(xr + base + j);
            m = fmaxf(m, fmaxf(fmaxf(fabsf(v[j].x), fabsf(v[j].y)),
                               fmaxf(fabsf(v[j].z), fabsf(v[j].w))));
        }
        #pragma unroll
        for (int o = 16; o; o >>= 1) m = fmaxf(m, __shfl_xor_sync(0xffffffffu, m, o));

        __shared__ float warpmax[8];
        __shared__ float s_inv;
        const int wid = threadIdx.x >> 5, lane = threadIdx.x & 31;
        if (lane == 0) warpmax[wid] = m;
        __syncthreads();
        if (threadIdx.x == 0) {
            float mm = warpmax[0];
            #pragma unroll
            for (int i = 1; i < 8; i++) mm = fmaxf(mm, warpmax[i]);
            float sc = fmaxf(mm, 1e-10f) / 127.0f;
            g_ascale[row] = sc;
            s_inv = 1.0f / sc;
        }
        __syncthreads();
        const float inv = s_inv;

        uint32_t p[4];
        #pragma unroll
        for (int j = 0; j < 4; j++) {
            char4 c = make_char4(q8(v[j].x, inv), q8(v[j].y, inv),
                                 q8(v[j].z, inv), q8(v[j].w, inv));
            p[j] = *reinterpret_cast<uint32_t*>(&c);
        }
        reinterpret_cast<uint4*>(g_xq + (size_t)row * KDIM)[threadIdx.x] =
            make_uint4(p[0], p[1], p[2], p[3]);
    } else {
        const size_t i = ((size_t)(blockIdx.x - T_TOKENS) * 256 + threadIdx.x) * 2;
        const float4* wp = reinterpret_cast<const float4*>(w);
        uint32_t p[2];
        #pragma unroll
        for (int j = 0; j < 2; j++) {
            const float4 v = ldcs4(wp + i + j);
            char4 c = make_char4((signed char)(int)v.x, (signed char)(int)v.y,
                                 (signed char)(int)v.z, (signed char)(int)v.w);
            p[j] = *reinterpret_cast<uint32_t*>(&c);
        }
        *reinterpret_cast<uint2*>(reinterpret_cast<char4*>(g_wq) + i) =
            make_uint2(p[0], p[1]);
    }
}

// ---------------------------------------------------------------------------
// K2: int8 GEMM. C[T,O] = xq[T,K] @ wq[O,K]^T     (R6, measured best)
// smem rows 64B = 4 chunks of 16B; swizzle: phys_chunk = c ^ ((row>>1)&3)
// ---------------------------------------------------------------------------
__global__ __launch_bounds__(128, 2)
void gemm_kernel(const float* __restrict__ wscale_p,
                 const float* __restrict__ bias,
                 float* __restrict__ out) {
    extern __shared__ int8_t smem_raw[];
    const uint32_t smem_u = (cvta_s(smem_raw) + 127u) & ~127u;

    const int tid  = threadIdx.x;
    const int lane = tid & 31;
    const int wid  = tid >> 5;
    const int wm   = wid & 1;
    const int wn   = wid >> 1;
    const int bm   = blockIdx.y;
    const int bn   = blockIdx.x;

    const int8_t* Ag = g_xq + (size_t)bm * BM * KDIM;
    const int8_t* Bg = g_wq + (size_t)bn * BN * KDIM;

    auto load_tile = [&](int st, int kt) {
        const uint32_t sb = smem_u + st * STAGE_BYTES;
        const int koff = kt * BK;
        #pragma unroll
        for (int r = 0; r < 4; r++) {
            const int id  = tid + (r << 7);
            const int row = id >> 2;
            const int c   = id & 3;
            const uint32_t phys = (uint32_t)((c ^ ((row >> 1) & 3)) << 4);
            cp_async16(sb + row * BK + phys,
                       Ag + (size_t)row * KDIM + koff + (c << 4));
            cp_async16(sb + A_BYTES + row * BK + phys,
                       Bg + (size_t)row * KDIM + koff + (c << 4));
        }
    };

    uint32_t a_off[4];
    {
        const int m  = lane >> 3;
        const int rr = ((m & 1) << 3) + (lane & 7);
        const int cb = m >> 1;
        #pragma unroll
        for (int mi = 0; mi < 4; mi++) {
            const int row = wm * 64 + mi * 16 + rr;
            a_off[mi] = (uint32_t)(row * BK + ((cb ^ ((row >> 1) & 3)) << 4));
        }
    }
    uint32_t b_off[4];
    {
        const int m  = lane >> 3;
        const int cr = ((m >> 1) << 3) + (lane & 7);
        const int cb = m & 1;
        #pragma unroll
        for (int n2 = 0; n2 < 4; n2++) {
            const int col = wn * 64 + n2 * 16 + cr;
            b_off[n2] = (uint32_t)(A_BYTES + col * BK + ((cb ^ ((col >> 1) & 3)) << 4));
        }
    }

    int acc[4][8][4] = {};

    load_tile(0, 0); cp_commit();
    load_tile(1, 1); cp_commit();
    load_tile(2, 2); cp_commit();

    for (int kt = 0; kt < KT; kt++) {
        cp_wait<2>();
        __syncthreads();

        const uint32_t sb = smem_u + (uint32_t)((kt & (NSTAGE - 1)) * STAGE_BYTES);

        uint32_t a[4][4], b[4][4];
        #pragma unroll
        for (int mi = 0; mi < 4; mi++) ldsm_x4(a[mi], sb + a_off[mi]);
        #pragma unroll
        for (int n2 = 0; n2 < 4; n2++)  ldsm_x4(b[n2], sb + b_off[n2]);

        const int nxt = kt + 3;
        if (nxt < KT) load_tile(nxt & (NSTAGE - 1), nxt);
        cp_commit();

        #pragma unroll
        for (int mi = 0; mi < 4; mi++) {
            #pragma unroll
            for (int ni = 0; ni < 8; ni++) {
                const uint32_t* bb = b[ni >> 1];
                const int o = (ni & 1) << 1;
                mma16832(acc[mi][ni], a[mi], bb[o], bb[o + 1]);
            }
        }

        #pragma unroll
        for (int mi = 0; mi < 4; mi++) ldsm_x4(a[mi], sb + (a_off[mi] ^ 32u));
        #pragma unroll
        for (int n2 = 0; n2 < 4; n2++)  ldsm_x4(b[n2], sb + (b_off[n2] ^ 32u));
        #pragma unroll
        for (int mi = 0; mi < 4; mi++) {
            #pragma unroll
            for (int ni = 0; ni < 8; ni++) {
                const uint32_t* bb = b[ni >> 1];
                const int o = (ni & 1) << 1;
                mma16832(acc[mi][ni], a[mi], bb[o], bb[o + 1]);
            }
        }
    }

    // epilogue: y = acc * act_scale[row] * w_scale + bias[col]
    const float ws = __ldg(wscale_p);
    #pragma unroll
    for (int mi = 0; mi < 4; mi++) {
        const int r0 = bm * BM + wm * 64 + mi * 16 + (lane >> 2);
        const float s0 = g_ascale[r0] * ws;
        const float s1 = g_ascale[r0 + 8] * ws;
        #pragma unroll
        for (int ni = 0; ni < 8; ni++) {
            const int c = bn * BN + wn * 64 + ni * 8 + ((lane & 3) << 1);
            const float b0 = __ldg(bias + c);
            const float b1 = __ldg(bias + c + 1);
            float2 v0 = make_float2((float)acc[mi][ni][0] * s0 + b0,
                                    (float)acc[mi][ni][1] * s0 + b1);
            float2 v1 = make_float2((float)acc[mi][ni][2] * s1 + b0,
                                    (float)acc[mi][ni][3] * s1 + b1);
            *reinterpret_cast<float2*>(out + (size_t)r0 * ODIM + c)       = v0;
            *reinterpret_cast<float2*>(out + (size_t)(r0 + 8) * ODIM + c) = v1;
        }
    }
}

// ---------------------------------------------------------------------------
extern "C" void kernel_launch(void* const* d_in, const int* in_sizes, int n_in,
                              void* d_out, int out_size) {
    const float* x      = (const float*)d_in[0];   // [8192, 4096]
    const float* w_t    = (const float*)d_in[1];   // [4096, 4096]
    const float* wscale = (const float*)d_in[2];   // scalar
    const float* bias   = (const float*)d_in[3];   // [4096]
    float* out          = (float*)d_out;           // [8192, 4096]

    quant_fused_kernel<<<T_TOKENS + W_BLOCKS, 256>>>(x, w_t);

    cudaFuncSetAttribute(gemm_kernel, cudaFuncAttributeMaxDynamicSharedMemorySize,
                         DYN_SMEM);
    dim3 grid(ODIM / BN, T_TOKENS / BM);   // (32, 64)
    gemm_kernel<<<grid, 128, DYN_SMEM>>>(wscale, bias, out);
}